// round 4
// baseline (speedup 1.0000x reference)
#include <cuda_runtime.h>

// ShortConvolution: depthwise causal conv K=4 + SiLU.
// x: (B=4, T=4096, D=2048) fp32 ; weight: (D=2048, K=4) fp32
// y[b,t,d] = silu( sum_{k=0..3} w[d,k] * x[b, t+k-3, d] )   (x[t<0] = 0)
//
// R4: TPT=8 (same traffic as R2: 11/8 L1 amplification, ~1x DRAM) but with a
//     7-slot circular x-buffer and refill loads interleaved into compute, so
//     only 7 float4 are live at once -> fits 51-reg bin -> 5 CTAs/SM.

#define B_ 4
#define T_ 4096
#define D_ 2048
#define DV_ (D_ / 4)        // 512 float4 lanes across channels
#define TPT_ 8              // time steps per thread
#define NCHUNK_ (T_ / TPT_) // 512

typedef unsigned long long u64;

__device__ __forceinline__ u64 pack2(float lo, float hi) {
    u64 r;
    asm("mov.b64 %0, {%1, %2};" : "=l"(r) : "f"(lo), "f"(hi));
    return r;
}
__device__ __forceinline__ void unpack2(u64 v, float& lo, float& hi) {
    asm("mov.b64 {%0, %1}, %2;" : "=f"(lo), "=f"(hi) : "l"(v));
}
__device__ __forceinline__ u64 fma2(u64 a, u64 b, u64 c) {
    u64 d;
    asm("fma.rn.f32x2 %0, %1, %2, %3;" : "=l"(d) : "l"(a), "l"(b), "l"(c));
    return d;
}
__device__ __forceinline__ u64 mul2(u64 a, u64 b) {
    u64 d;
    asm("mul.rn.f32x2 %0, %1, %2;" : "=l"(d) : "l"(a), "l"(b));
    return d;
}
__device__ __forceinline__ float tanh_fast(float v) {
    float r;
    asm("tanh.approx.f32 %0, %1;" : "=f"(r) : "f"(v));
    return r;
}

__global__ __launch_bounds__(256, 5)
void shortconv_silu_kernel(const float4* __restrict__ x,
                           const float4* __restrict__ w,
                           float4* __restrict__ out) {
    const int gid = blockIdx.x * blockDim.x + threadIdx.x;
    const int dv  = gid % DV_;              // float4 lane along channels
    const int row = gid / DV_;              // (b, t-chunk)
    const int t0  = (row % NCHUNK_) * TPT_;
    const int b   = row / NCHUNK_;

    // weight layout (D, K): float4 w[c] = the 4 taps of channel c.
    const float4 wa = __ldg(&w[4 * dv + 0]);
    const float4 wb = __ldg(&w[4 * dv + 1]);
    const float4 wc = __ldg(&w[4 * dv + 2]);
    const float4 wd = __ldg(&w[4 * dv + 3]);

    // Packed taps: lo = channels (.x,.y), hi = channels (.z,.w)
    const u64 wlo0 = pack2(wa.x, wb.x), wlo1 = pack2(wa.y, wb.y);
    const u64 wlo2 = pack2(wa.z, wb.z), wlo3 = pack2(wa.w, wb.w);
    const u64 whi0 = pack2(wc.x, wd.x), whi1 = pack2(wc.y, wd.y);
    const u64 whi2 = pack2(wc.z, wd.z), whi3 = pack2(wc.w, wd.w);

    const u64 HALF2 = pack2(0.5f, 0.5f);

    const size_t base = (size_t)b * T_ * DV_ + dv;
    const float4* __restrict__ xp = x + base;
    float4* __restrict__ op = out + base;

    // 7-slot circular buffer: xs[k] lives in slot k % 7.
    u64 xlo[7], xhi[7];

    // Initial fill: xs[0..6] = x[t0-3 .. t0+3] (zero for t<0).
#pragma unroll
    for (int i = 0; i < 7; ++i) {
        const int t = t0 + i - 3;
        float4 v = make_float4(0.f, 0.f, 0.f, 0.f);
        if (t >= 0) v = __ldg(&xp[(size_t)t * DV_]);
        xlo[i] = pack2(v.x, v.y);
        xhi[i] = pack2(v.z, v.w);
    }

#pragma unroll
    for (int j = 0; j < TPT_; ++j) {
        const int s0 = (j + 0) % 7;
        const int s1 = (j + 1) % 7;
        const int s2 = (j + 2) % 7;
        const int s3 = (j + 3) % 7;

        // y = w0*x[j] + w1*x[j+1] + w2*x[j+2] + w3*x[j+3]
        u64 alo = mul2(wlo3, xlo[s3]);
        alo = fma2(wlo2, xlo[s2], alo);
        alo = fma2(wlo1, xlo[s1], alo);
        alo = fma2(wlo0, xlo[s0], alo);

        u64 ahi = mul2(whi3, xhi[s3]);
        ahi = fma2(whi2, xhi[s2], ahi);
        ahi = fma2(whi1, xhi[s1], ahi);
        ahi = fma2(whi0, xhi[s0], ahi);

        // Refill: slot s0 (= xs[j]) is now dead; load xs[7+j] into it.
        // t = t0 + (7+j) - 3 = t0 + 4 + j, always in [4, T-1] -> no guard.
        if (j < 4) {
            const float4 v = __ldg(&xp[(size_t)(t0 + 4 + j) * DV_]);
            xlo[s0] = pack2(v.x, v.y);
            xhi[s0] = pack2(v.z, v.w);
        }

        // SiLU: y * (0.5*tanh(0.5*y) + 0.5)   (single MUFU per element)
        u64 hlo = mul2(alo, HALF2);
        u64 hhi = mul2(ahi, HALF2);
        float h0, h1, h2, h3;
        unpack2(hlo, h0, h1);
        unpack2(hhi, h2, h3);
        const u64 tlo = pack2(tanh_fast(h0), tanh_fast(h1));
        const u64 thi = pack2(tanh_fast(h2), tanh_fast(h3));
        const u64 slo = fma2(tlo, HALF2, HALF2);
        const u64 shi = fma2(thi, HALF2, HALF2);
        const u64 ylo = mul2(alo, slo);
        const u64 yhi = mul2(ahi, shi);

        float4 o;
        unpack2(ylo, o.x, o.y);
        unpack2(yhi, o.z, o.w);
        op[(size_t)(t0 + j) * DV_] = o;
    }
}

extern "C" void kernel_launch(void* const* d_in, const int* in_sizes, int n_in,
                              void* d_out, int out_size) {
    const float4* x = (const float4*)d_in[0];
    const float4* w = (const float4*)d_in[1];
    float4* out = (float4*)d_out;

    const int total_threads = B_ * NCHUNK_ * DV_;   // 4 * 512 * 512 = 1,048,576
    const int block = 256;
    const int grid = total_threads / block;          // 4096

    shortconv_silu_kernel<<<grid, block>>>(x, w, out);
}

// round 5
// speedup vs baseline: 1.0499x; 1.0499x over previous
#include <cuda_runtime.h>

// ShortConvolution: depthwise causal conv K=4 + SiLU.
// x: (B=4, T=4096, D=2048) fp32 ; weight: (D=2048, K=4) fp32
// y[b,t,d] = silu( sum_{k=0..3} w[d,k] * x[b, t+k-3, d] )   (x[t<0] = 0)
//
// R5: cp.async double-buffered time pipeline. Each thread owns (b, dv) and 4
//     consecutive 8-step chunks. While chunk i is computed from smem stage
//     i&1, the 8 loads of chunk i+1 are in flight into the other stage ->
//     DRAM never idles between load/compute phases. Halo (3 samples) carries
//     across chunks in a register ring -> DRAM read amplification = 1.0.

#define B_ 4
#define T_ 4096
#define D_ 2048
#define DV_ (D_ / 4)        // 512 float4 lanes across channels
#define TPT_ 8              // time steps per chunk
#define NITER_ 4            // chunks per thread
#define NGROUP_ (T_ / (TPT_ * NITER_))   // 128 groups per batch
#define BLOCK_ 128

typedef unsigned long long u64;

__device__ __forceinline__ u64 pack2(float lo, float hi) {
    u64 r;
    asm("mov.b64 %0, {%1, %2};" : "=l"(r) : "f"(lo), "f"(hi));
    return r;
}
__device__ __forceinline__ void unpack2(u64 v, float& lo, float& hi) {
    asm("mov.b64 {%0, %1}, %2;" : "=f"(lo), "=f"(hi) : "l"(v));
}
__device__ __forceinline__ u64 fma2(u64 a, u64 b, u64 c) {
    u64 d;
    asm("fma.rn.f32x2 %0, %1, %2, %3;" : "=l"(d) : "l"(a), "l"(b), "l"(c));
    return d;
}
__device__ __forceinline__ u64 mul2(u64 a, u64 b) {
    u64 d;
    asm("mul.rn.f32x2 %0, %1, %2;" : "=l"(d) : "l"(a), "l"(b));
    return d;
}
__device__ __forceinline__ float tanh_fast(float v) {
    float r;
    asm("tanh.approx.f32 %0, %1;" : "=f"(r) : "f"(v));
    return r;
}
__device__ __forceinline__ void cp_async16(unsigned int smem_dst, const void* gsrc) {
    asm volatile("cp.async.cg.shared.global [%0], [%1], 16;"
                 :: "r"(smem_dst), "l"(gsrc) : "memory");
}
__device__ __forceinline__ void cp_commit() {
    asm volatile("cp.async.commit_group;" ::: "memory");
}

__global__ __launch_bounds__(BLOCK_)
void shortconv_silu_kernel(const float4* __restrict__ x,
                           const float4* __restrict__ w,
                           float4* __restrict__ out) {
    // smem: [stage][slot][thread] -> lane-contiguous 16B, conflict-free LDS.128
    __shared__ float4 tile[2][TPT_][BLOCK_];

    const int tid = threadIdx.x;
    const int gid = blockIdx.x * BLOCK_ + tid;
    const int dv  = gid % DV_;               // float4 lane along channels
    const int row = gid / DV_;               // (b, group)
    const int g   = row % NGROUP_;
    const int b   = row / NGROUP_;
    const int t0  = g * (TPT_ * NITER_);     // first output timestep

    // weight layout (D, K): float4 w[c] = the 4 taps of channel c.
    const float4 wa = __ldg(&w[4 * dv + 0]);
    const float4 wb = __ldg(&w[4 * dv + 1]);
    const float4 wc = __ldg(&w[4 * dv + 2]);
    const float4 wd = __ldg(&w[4 * dv + 3]);

    // Packed taps: lo = channels (.x,.y), hi = channels (.z,.w)
    const u64 wlo0 = pack2(wa.x, wb.x), wlo1 = pack2(wa.y, wb.y);
    const u64 wlo2 = pack2(wa.z, wb.z), wlo3 = pack2(wa.w, wb.w);
    const u64 whi0 = pack2(wc.x, wd.x), whi1 = pack2(wc.y, wd.y);
    const u64 whi2 = pack2(wc.z, wd.z), whi3 = pack2(wc.w, wd.w);

    const u64 HALF2 = pack2(0.5f, 0.5f);

    const size_t base = (size_t)b * T_ * DV_ + dv;
    const float4* __restrict__ xp = x + base;
    float4* __restrict__ op = out + base;

    // Halo ring: a = x[t-3], bb = x[t-2], cc = x[t-1] (zeros for t<0).
    u64 alo = 0, ahi = 0, blo_ = 0, bhi_ = 0, clo = 0, chi = 0;
    if (t0 >= 3) {  // t0 == 0 only for g == 0; otherwise t0 >= 32
        float4 va = __ldg(&xp[(size_t)(t0 - 3) * DV_]);
        float4 vb = __ldg(&xp[(size_t)(t0 - 2) * DV_]);
        float4 vc = __ldg(&xp[(size_t)(t0 - 1) * DV_]);
        alo  = pack2(va.x, va.y); ahi  = pack2(va.z, va.w);
        blo_ = pack2(vb.x, vb.y); bhi_ = pack2(vb.z, vb.w);
        clo  = pack2(vc.x, vc.y); chi  = pack2(vc.z, vc.w);
    }

    // Prefetch stage 0 <- x[t0 .. t0+7]
#pragma unroll
    for (int s = 0; s < TPT_; ++s) {
        cp_async16((unsigned int)__cvta_generic_to_shared(&tile[0][s][tid]),
                   &xp[(size_t)(t0 + s) * DV_]);
    }
    cp_commit();

#pragma unroll
    for (int i = 0; i < NITER_; ++i) {
        const int ti0 = t0 + i * TPT_;

        // Prefetch next stage while this one is consumed.
        if (i + 1 < NITER_) {
            const int tn0 = ti0 + TPT_;
#pragma unroll
            for (int s = 0; s < TPT_; ++s) {
                cp_async16((unsigned int)__cvta_generic_to_shared(&tile[(i + 1) & 1][s][tid]),
                           &xp[(size_t)(tn0 + s) * DV_]);
            }
            cp_commit();
            asm volatile("cp.async.wait_group 1;" ::: "memory");  // stage i ready
        } else {
            asm volatile("cp.async.wait_group 0;" ::: "memory");  // last stage ready
        }

#pragma unroll
        for (int j = 0; j < TPT_; ++j) {
            const float4 d4 = tile[i & 1][j][tid];
            const u64 dlo = pack2(d4.x, d4.y);
            const u64 dhi = pack2(d4.z, d4.w);

            // y[t] = w0*x[t-3] + w1*x[t-2] + w2*x[t-1] + w3*x[t]
            u64 ylo = mul2(wlo3, dlo);
            ylo = fma2(wlo2, clo,  ylo);
            ylo = fma2(wlo1, blo_, ylo);
            ylo = fma2(wlo0, alo,  ylo);

            u64 yhi = mul2(whi3, dhi);
            yhi = fma2(whi2, chi,  yhi);
            yhi = fma2(whi1, bhi_, yhi);
            yhi = fma2(whi0, ahi,  yhi);

            // SiLU: y * (0.5*tanh(0.5*y) + 0.5)  (single MUFU per element)
            const u64 hlo = mul2(ylo, HALF2);
            const u64 hhi = mul2(yhi, HALF2);
            float h0, h1, h2, h3;
            unpack2(hlo, h0, h1);
            unpack2(hhi, h2, h3);
            const u64 tlo = pack2(tanh_fast(h0), tanh_fast(h1));
            const u64 thi = pack2(tanh_fast(h2), tanh_fast(h3));
            const u64 slo = fma2(tlo, HALF2, HALF2);
            const u64 shi = fma2(thi, HALF2, HALF2);
            const u64 olo = mul2(ylo, slo);
            const u64 ohi = mul2(yhi, shi);

            float4 o;
            unpack2(olo, o.x, o.y);
            unpack2(ohi, o.z, o.w);
            op[(size_t)(ti0 + j) * DV_] = o;

            // Slide halo ring: a <- b <- c <- d
            alo = blo_; ahi = bhi_;
            blo_ = clo; bhi_ = chi;
            clo = dlo;  chi = dhi;
        }
    }
}

extern "C" void kernel_launch(void* const* d_in, const int* in_sizes, int n_in,
                              void* d_out, int out_size) {
    const float4* x = (const float4*)d_in[0];
    const float4* w = (const float4*)d_in[1];
    float4* out = (float4*)d_out;

    const int total_threads = B_ * NGROUP_ * DV_;   // 4 * 128 * 512 = 262,144
    const int grid = total_threads / BLOCK_;         // 2048

    shortconv_silu_kernel<<<grid, BLOCK_>>>(x, w, out);
}